// round 8
// baseline (speedup 1.0000x reference)
#include <cuda_runtime.h>

#define N_NODES 100000
#define N_EDGES 3200000

#define EDGE_BLOCKS ((N_EDGES + 255) / 256)   // 12500
#define NODE_BLOCKS ((N_NODES + 255) / 256)   // 391

// Per-node projected aggregate. Invariant: zero at kernel_launch entry
// (zero-init at load; node phase re-zeros after consuming each replay).
__device__ float2 g_z[N_NODES];
// Ticket counter. Invariant: zero at entry; last node-block resets it.
__device__ unsigned g_ctr;

__global__ void __launch_bounds__(256) fused_kernel(
    const float4* __restrict__ ea,   // edge_attr as float4[N_EDGES*4]
    const int* __restrict__ col,     // edge_index row 1 (dst), int32
    const float* __restrict__ x,
    const float* __restrict__ W1,    // [19,2] row-major
    const float* __restrict__ b1,
    const float* __restrict__ W2,    // [2,3] row-major
    const float* __restrict__ b2,
    float* __restrict__ out)
{
    const int tid = threadIdx.x;

    // ---------------- Edge phase ----------------
    {
        float w0[16], w1[16];
#pragma unroll
        for (int k = 0; k < 16; k++) {
            w0[k] = __ldg(&W1[(3 + k) * 2 + 0]);
            w1[k] = __ldg(&W1[(3 + k) * 2 + 1]);
        }

        const int e = blockIdx.x * 256 + tid;
        if (e < N_EDGES) {
            const float4 a = ea[e * 4 + 0];
            const float4 b = ea[e * 4 + 1];
            const float4 c = ea[e * 4 + 2];
            const float4 d = ea[e * 4 + 3];

            float p0 = a.x * w0[0]  + a.y * w0[1]  + a.z * w0[2]  + a.w * w0[3]
                     + b.x * w0[4]  + b.y * w0[5]  + b.z * w0[6]  + b.w * w0[7]
                     + c.x * w0[8]  + c.y * w0[9]  + c.z * w0[10] + c.w * w0[11]
                     + d.x * w0[12] + d.y * w0[13] + d.z * w0[14] + d.w * w0[15];

            float p1 = a.x * w1[0]  + a.y * w1[1]  + a.z * w1[2]  + a.w * w1[3]
                     + b.x * w1[4]  + b.y * w1[5]  + b.z * w1[6]  + b.w * w1[7]
                     + c.x * w1[8]  + c.y * w1[9]  + c.z * w1[10] + c.w * w1[11]
                     + d.x * w1[12] + d.y * w1[13] + d.z * w1[14] + d.w * w1[15];

            const int node = col[e];
            if ((unsigned)node < (unsigned)N_NODES)
                atomicAdd(&g_z[node], make_float2(p0, p1));  // RED.ADD.F32x2
        }
    }

    // ---------------- Ticket ----------------
    __syncthreads();
    __shared__ unsigned s_ticket;
    if (tid == 0) {
        __threadfence();                       // release: REDs visible before count
        s_ticket = atomicAdd(&g_ctr, 1u);
    }
    __syncthreads();
    const unsigned ticket = s_ticket;

    // Only the last NODE_BLOCKS finishers do node work.
    if (ticket < (unsigned)(EDGE_BLOCKS - NODE_BLOCKS)) return;

    // ---------------- Node phase (overlaps remaining edge blocks) ----------------
    const int chunk = (int)ticket - (EDGE_BLOCKS - NODE_BLOCKS);
    const int i = chunk * 256 + tid;
    const bool active = (i < N_NODES);

    float x0 = 0.f, x1 = 0.f, x2 = 0.f;
    if (active) {
        x0 = x[i * 3 + 0];
        x1 = x[i * 3 + 1];
        x2 = x[i * 3 + 2];
    }

    // x-only math — computed while other blocks still run edge phase.
    const float vi = x0, s1 = x1, s2 = x2;

    const float n1 = (__powf(0.7660379f, s2 * (1.0f / 0.3038425f) + s1)
                      + __powf(0.12117091f, s1) * (1.0f / -0.7256157f))
                     * __powf(1.2125463f, vi) + 0.12262904f;

    const float t = s2 + (s1 + (-3.283101f) - vi * (1.0f / 0.79082423f)) * 0.31992579f;
    const float n1_n2 = 0.7872602f - sqrtf(__logf(__powf(0.1562228f, t) + 1.4462701f));

    const float h0x = b1[0] + x0 * W1[0] + x1 * W1[2] + x2 * W1[4];
    const float h1x = b1[1] + x0 * W1[1] + x1 * W1[3] + x2 * W1[5];
    const float w20 = W2[2], w21 = W2[5], bb2 = b2[2];

    // Wait for all edge blocks to have fenced + ticketed.
    if (tid == 0) {
        while (*(volatile unsigned*)&g_ctr < (unsigned)EDGE_BLOCKS)
            __nanosleep(64);
    }
    __syncthreads();
    __threadfence();                           // acquire: see all REDs

    if (active) {
        const float2 z = g_z[i];
        g_z[i] = make_float2(0.0f, 0.0f);      // restore zero-invariant

        const float h0 = fmaxf(h0x + z.x, 0.0f);
        const float h1 = fmaxf(h1x + z.y, 0.0f);
        const float o2 = h0 * w20 + h1 * w21 + bb2 + x2;

        out[i * 3 + 0] = n1 + x0;
        out[i * 3 + 1] = (n1_n2 - n1) + x1;
        out[i * 3 + 2] = o2;
    }

    // Completion count; last node-block resets the counter for next replay.
    __syncthreads();
    if (tid == 0) {
        __threadfence();
        const unsigned done = atomicAdd(&g_ctr, 1u);
        if (done == (unsigned)(EDGE_BLOCKS + NODE_BLOCKS - 1)) {
            g_ctr = 0u;                        // all spinners already exited
            __threadfence();
        }
    }
}

extern "C" void kernel_launch(void* const* d_in, const int* in_sizes, int n_in,
                              void* d_out, int out_size) {
    // Inputs: 0:x 1:edge_attr 2:u 3:W1 4:b1 5:W2 6:b2 7:edge_index 8:batch
    const float*  x    = (const float*)d_in[0];
    const float4* ea   = (const float4*)d_in[1];
    const float*  W1   = (const float*)d_in[3];
    const float*  b1   = (const float*)d_in[4];
    const float*  W2   = (const float*)d_in[5];
    const float*  b2   = (const float*)d_in[6];
    const int*    eidx = (const int*)d_in[7];   // int64 ref -> int32 device
    float*        out  = (float*)d_out;

    const int* col = eidx + N_EDGES;  // edge_index[1, :]

    fused_kernel<<<EDGE_BLOCKS, 256>>>(ea, col, x, W1, b1, W2, b2, out);
}

// round 12
// speedup vs baseline: 1.0331x; 1.0331x over previous
#include <cuda_runtime.h>

#define N_NODES 100000
#define N_EDGES 3200000

// Per-node projected aggregate. Invariant: zero at kernel_launch entry
// (zero-init at load; node_kernel re-zeros after consuming each replay).
__device__ float2 g_z[N_NODES];

// 4 threads per edge. Thread t: edge e = t>>2, quarter q = t&3.
// Lane l loads ea[t] -> fully coalesced 512B per warp per LDG.128.
__global__ void __launch_bounds__(256) edge_kernel(
    const float4* __restrict__ ea,   // edge_attr as float4[N_EDGES*4]
    const int* __restrict__ col,     // edge_index row 1 (dst), int32
    const float* __restrict__ W1)    // [19,2] row-major
{
    const int t = blockIdx.x * 256 + threadIdx.x;   // grid sized exactly: no bounds check needed
    const int q = t & 3;

    // This quarter's 4 weight rows (rows 3+4q .. 6+4q), cols 0/1.
    // Only 4 distinct address sets per warp -> L1 broadcast hits.
    const int wbase = (3 + 4 * q) * 2;
    const float wa0 = __ldg(&W1[wbase + 0]), wa1 = __ldg(&W1[wbase + 1]);
    const float wb0 = __ldg(&W1[wbase + 2]), wb1 = __ldg(&W1[wbase + 3]);
    const float wc0 = __ldg(&W1[wbase + 4]), wc1 = __ldg(&W1[wbase + 5]);
    const float wd0 = __ldg(&W1[wbase + 6]), wd1 = __ldg(&W1[wbase + 7]);

    const float4 v = ea[t];

    float p0 = v.x * wa0 + v.y * wb0 + v.z * wc0 + v.w * wd0;
    float p1 = v.x * wa1 + v.y * wb1 + v.z * wc1 + v.w * wd1;

    // Quad reduction (lanes q=0..3 of each edge are adjacent).
    p0 += __shfl_xor_sync(0xffffffffu, p0, 1);
    p1 += __shfl_xor_sync(0xffffffffu, p1, 1);
    p0 += __shfl_xor_sync(0xffffffffu, p0, 2);
    p1 += __shfl_xor_sync(0xffffffffu, p1, 2);

    if (q == 0) {
        const int node = col[t >> 2];
        if ((unsigned)node < (unsigned)N_NODES)
            atomicAdd(&g_z[node], make_float2(p0, p1));  // RED.ADD.F32x2
    }
}

__global__ void __launch_bounds__(256) node_kernel(
    const float* __restrict__ x,
    const float* __restrict__ W1,
    const float* __restrict__ b1,
    const float* __restrict__ W2,
    const float* __restrict__ b2,
    float* __restrict__ out)
{
    const int i = blockIdx.x * blockDim.x + threadIdx.x;
    if (i >= N_NODES) return;

    const float x0 = x[i * 3 + 0];
    const float x1 = x[i * 3 + 1];
    const float x2 = x[i * 3 + 2];

    const float2 z = g_z[i];
    g_z[i] = make_float2(0.0f, 0.0f);   // restore zero-invariant for next replay

    float h0 = b1[0] + x0 * W1[0] + x1 * W1[2] + x2 * W1[4] + z.x;
    float h1 = b1[1] + x0 * W1[1] + x1 * W1[3] + x2 * W1[5] + z.y;
    h0 = fmaxf(h0, 0.0f);
    h1 = fmaxf(h1, 0.0f);

    // Only MLP output column 2 survives. W2 is [2,3] row-major.
    const float o2 = h0 * W2[2] + h1 * W2[5] + b2[2] + x2;

    const float vi = x0, s1 = x1, s2 = x2;

    const float n1 = (__powf(0.7660379f, s2 * (1.0f / 0.3038425f) + s1)
                      + __powf(0.12117091f, s1) * (1.0f / -0.7256157f))
                     * __powf(1.2125463f, vi) + 0.12262904f;

    const float t = s2 + (s1 + (-3.283101f) - vi * (1.0f / 0.79082423f)) * 0.31992579f;
    const float n1_n2 = 0.7872602f - sqrtf(__logf(__powf(0.1562228f, t) + 1.4462701f));

    out[i * 3 + 0] = n1 + x0;
    out[i * 3 + 1] = (n1_n2 - n1) + x1;
    out[i * 3 + 2] = o2;
}

extern "C" void kernel_launch(void* const* d_in, const int* in_sizes, int n_in,
                              void* d_out, int out_size) {
    // Inputs: 0:x 1:edge_attr 2:u 3:W1 4:b1 5:W2 6:b2 7:edge_index 8:batch
    const float*  x    = (const float*)d_in[0];
    const float4* ea   = (const float4*)d_in[1];
    const float*  W1   = (const float*)d_in[3];
    const float*  b1   = (const float*)d_in[4];
    const float*  W2   = (const float*)d_in[5];
    const float*  b2   = (const float*)d_in[6];
    const int*    eidx = (const int*)d_in[7];   // int64 ref -> int32 device
    float*        out  = (float*)d_out;

    const int* col = eidx + N_EDGES;  // edge_index[1, :]

    // 4*N_EDGES threads, exactly divisible by 256 -> 50000 blocks.
    edge_kernel<<<(4 * N_EDGES) / 256, 256>>>(ea, col, W1);
    node_kernel<<<(N_NODES + 255) / 256, 256>>>(x, W1, b1, W2, b2, out);
}

// round 14
// speedup vs baseline: 1.1474x; 1.1107x over previous
#include <cuda_runtime.h>

#define N_NODES 100000
#define N_EDGES 3200000
#define EPB 256   // edges per block (== blockDim)

// Per-node projected aggregate. Invariant: zero at kernel_launch entry
// (zero-init at load; node_kernel re-zeros after consuming each replay).
__device__ float2 g_z[N_NODES];

// 1 thread per edge, but edge_attr is staged through shared memory:
// Phase 1: 4 fully-coalesced LDG.128 passes pull the block's 16KB tile.
// Phase 2: each thread reads its edge's 4 float4s from smem (stride-5
// padding -> conflict-free LDS.128) and does the 32-FMA projection + 1 RED.
__global__ void __launch_bounds__(256) edge_kernel(
    const float4* __restrict__ ea,   // edge_attr as float4[N_EDGES*4]
    const int* __restrict__ col,     // edge_index row 1 (dst), int32
    const float* __restrict__ W1)    // [19,2] row-major
{
    __shared__ float4 s[EPB * 5];    // slot(e,j) = e*5 + j, j=0..3 (5th = pad)

    const int tid = threadIdx.x;

    // Weights (rows 3..18, cols 0/1) -> registers. Uniform addresses: broadcast hits.
    float w0[16], w1[16];
#pragma unroll
    for (int k = 0; k < 16; k++) {
        w0[k] = __ldg(&W1[(3 + k) * 2 + 0]);
        w1[k] = __ldg(&W1[(3 + k) * 2 + 1]);
    }

    // ---- Phase 1: coalesced tile load (grid is exact: no bounds checks) ----
    const int base = blockIdx.x * (EPB * 4);   // float4 units
#pragma unroll
    for (int p = 0; p < 4; p++) {
        const int g = p * EPB + tid;           // 0..1023 within tile
        s[(g >> 2) * 5 + (g & 3)] = ea[base + g];
    }
    __syncthreads();

    // ---- Phase 2: per-edge projection ----
    const float4 a = s[tid * 5 + 0];
    const float4 b = s[tid * 5 + 1];
    const float4 c = s[tid * 5 + 2];
    const float4 d = s[tid * 5 + 3];

    const float p0 = a.x * w0[0]  + a.y * w0[1]  + a.z * w0[2]  + a.w * w0[3]
                   + b.x * w0[4]  + b.y * w0[5]  + b.z * w0[6]  + b.w * w0[7]
                   + c.x * w0[8]  + c.y * w0[9]  + c.z * w0[10] + c.w * w0[11]
                   + d.x * w0[12] + d.y * w0[13] + d.z * w0[14] + d.w * w0[15];

    const float p1 = a.x * w1[0]  + a.y * w1[1]  + a.z * w1[2]  + a.w * w1[3]
                   + b.x * w1[4]  + b.y * w1[5]  + b.z * w1[6]  + b.w * w1[7]
                   + c.x * w1[8]  + c.y * w1[9]  + c.z * w1[10] + c.w * w1[11]
                   + d.x * w1[12] + d.y * w1[13] + d.z * w1[14] + d.w * w1[15];

    const int node = col[blockIdx.x * EPB + tid];
    if ((unsigned)node < (unsigned)N_NODES)
        atomicAdd(&g_z[node], make_float2(p0, p1));  // RED.ADD.F32x2
}

__global__ void __launch_bounds__(256) node_kernel(
    const float* __restrict__ x,
    const float* __restrict__ W1,
    const float* __restrict__ b1,
    const float* __restrict__ W2,
    const float* __restrict__ b2,
    float* __restrict__ out)
{
    const int i = blockIdx.x * blockDim.x + threadIdx.x;
    if (i >= N_NODES) return;

    const float x0 = x[i * 3 + 0];
    const float x1 = x[i * 3 + 1];
    const float x2 = x[i * 3 + 2];

    const float2 z = g_z[i];
    g_z[i] = make_float2(0.0f, 0.0f);   // restore zero-invariant for next replay

    float h0 = b1[0] + x0 * W1[0] + x1 * W1[2] + x2 * W1[4] + z.x;
    float h1 = b1[1] + x0 * W1[1] + x1 * W1[3] + x2 * W1[5] + z.y;
    h0 = fmaxf(h0, 0.0f);
    h1 = fmaxf(h1, 0.0f);

    // Only MLP output column 2 survives. W2 is [2,3] row-major.
    const float o2 = h0 * W2[2] + h1 * W2[5] + b2[2] + x2;

    const float vi = x0, s1 = x1, s2 = x2;

    const float n1 = (__powf(0.7660379f, s2 * (1.0f / 0.3038425f) + s1)
                      + __powf(0.12117091f, s1) * (1.0f / -0.7256157f))
                     * __powf(1.2125463f, vi) + 0.12262904f;

    const float t = s2 + (s1 + (-3.283101f) - vi * (1.0f / 0.79082423f)) * 0.31992579f;
    const float n1_n2 = 0.7872602f - sqrtf(__logf(__powf(0.1562228f, t) + 1.4462701f));

    out[i * 3 + 0] = n1 + x0;
    out[i * 3 + 1] = (n1_n2 - n1) + x1;
    out[i * 3 + 2] = o2;
}

extern "C" void kernel_launch(void* const* d_in, const int* in_sizes, int n_in,
                              void* d_out, int out_size) {
    // Inputs: 0:x 1:edge_attr 2:u 3:W1 4:b1 5:W2 6:b2 7:edge_index 8:batch
    const float*  x    = (const float*)d_in[0];
    const float4* ea   = (const float4*)d_in[1];
    const float*  W1   = (const float*)d_in[3];
    const float*  b1   = (const float*)d_in[4];
    const float*  W2   = (const float*)d_in[5];
    const float*  b2   = (const float*)d_in[6];
    const int*    eidx = (const int*)d_in[7];   // int64 ref -> int32 device
    float*        out  = (float*)d_out;

    const int* col = eidx + N_EDGES;  // edge_index[1, :]

    edge_kernel<<<N_EDGES / EPB, EPB>>>(ea, col, W1);   // 12500 blocks, exact
    node_kernel<<<(N_NODES + 255) / 256, 256>>>(x, W1, b1, W2, b2, out);
}